// round 16
// baseline (speedup 1.0000x reference)
#include <cuda_runtime.h>
#include <math.h>

#define H    512
#define NH   8
#define DH   64
#define NLAY 2
#define NPRED 26
#define MAXF 5
#define FFD  2048
#define BSZ  16
#define TC   10
#define NOBJ 20
#define NP   380   /* NOBJ*(NOBJ-1) */
#define SP   516   /* padded smem row (floats) */

// ---------------- scratch (device globals; no allocation) ----------------
__device__ __align__(16) float g_px  [BSZ*MAXF*H];
__device__ __align__(16) float g_qkv [BSZ*MAXF*3*H];
__device__ __align__(16) float g_kv  [NLAY*BSZ*TC*2*H];
__device__ __align__(16) float g_proj[4*BSZ*MAXF*H];   // up to 4 K-split slices
__device__ __align__(16) float g_ffh [BSZ*MAXF*FFD];
__device__ __align__(16) float g_ctx [BSZ*MAXF*H];
__device__ __align__(16) float g_sw  [BSZ*NOBJ*H];
__device__ __align__(16) float g_ow  [BSZ*NOBJ*H];
__device__ __align__(16) float g_cw  [BSZ*MAXF*H];
__device__ __align__(16) float g_wf  [32*H];           // rows 27..31 zero
__device__ float g_bf [32];

__device__ __forceinline__ float gelu_f(float x) {
    return 0.5f * x * (1.0f + erff(x * 0.70710678118654752440f));
}
__device__ __forceinline__ float wred(float v) {
    v += __shfl_xor_sync(0xffffffffu, v, 16);
    v += __shfl_xor_sync(0xffffffffu, v, 8);
    v += __shfl_xor_sync(0xffffffffu, v, 4);
    v += __shfl_xor_sync(0xffffffffu, v, 2);
    v += __shfl_xor_sync(0xffffffffu, v, 1);
    return v;
}

// ---------------- 3xTF32 mma primitives --------------------------------------
__device__ __forceinline__ unsigned tf32_of(float v) {
    unsigned r;
    asm("cvt.rna.tf32.f32 %0, %1;" : "=r"(r) : "f"(v));
    return r;
}
__device__ __forceinline__ void split32(float v, unsigned& h, unsigned& l) {
    h = tf32_of(v);
    float lf = v - __uint_as_float(h);
    l = tf32_of(lf);
}
__device__ __forceinline__ void mma_tf32(float* d, unsigned a0, unsigned a1,
                                         unsigned a2, unsigned a3,
                                         unsigned b0, unsigned b1) {
    asm("mma.sync.aligned.m16n8k8.row.col.f32.tf32.tf32.f32 "
        "{%0,%1,%2,%3},{%4,%5,%6,%7},{%8,%9},{%0,%1,%2,%3};"
        : "+f"(d[0]), "+f"(d[1]), "+f"(d[2]), "+f"(d[3])
        : "r"(a0), "r"(a1), "r"(a2), "r"(a3), "r"(b0), "r"(b1));
}
__device__ __forceinline__ void mma3x(float* d, const unsigned* ah, const unsigned* al,
                                      unsigned bh0, unsigned bh1,
                                      unsigned bl0, unsigned bl1) {
    mma_tf32(d, al[0], al[1], al[2], al[3], bh0, bh1);
    mma_tf32(d, ah[0], ah[1], ah[2], ah[3], bl0, bl1);
    mma_tf32(d, ah[0], ah[1], ah[2], ah[3], bh0, bh1);
}

// ---------------- tensor GEMM tile body (128 thr = 4 warps, 16m x 16n) -------
__device__ void tgemm_body(const float* __restrict__ A, int lda,
                           const float* __restrict__ W, int ldw,
                           const float* __restrict__ bias,
                           float* __restrict__ C, int M, int N, int act, int bcmod,
                           int m0, int n0, int k0, int klen, float* red)
{
    int tid = threadIdx.x, warp = tid >> 5, lane = tid & 31;
    int g = lane >> 2, t = lane & 3;
    int Kw = klen >> 2;
    int kb = k0 + warp * Kw;
    int r0 = m0 + g, r1 = m0 + g + 8;
    int mm0 = bcmod ? (r0 % bcmod) : (r0 < M ? r0 : M - 1);
    int mm1 = bcmod ? (r1 % bcmod) : (r1 < M ? r1 : M - 1);
    const float* a0p = A + (long)mm0 * lda;
    const float* a1p = A + (long)mm1 * lda;
    const float* b0p = W + (long)(n0 + g) * ldw;
    const float* b1p = W + (long)(n0 + 8 + g) * ldw;

    float d0[4] = {0.f, 0.f, 0.f, 0.f};
    float d1[4] = {0.f, 0.f, 0.f, 0.f};

    #pragma unroll 4
    for (int kk = kb; kk < kb + Kw; kk += 8) {
        unsigned ah[4], al[4];
        split32(a0p[kk + t],     ah[0], al[0]);
        split32(a1p[kk + t],     ah[1], al[1]);
        split32(a0p[kk + t + 4], ah[2], al[2]);
        split32(a1p[kk + t + 4], ah[3], al[3]);
        unsigned bh0, bl0, bh1, bl1, ch0, cl0, ch1, cl1;
        split32(b0p[kk + t],     bh0, bl0);
        split32(b0p[kk + t + 4], bh1, bl1);
        split32(b1p[kk + t],     ch0, cl0);
        split32(b1p[kk + t + 4], ch1, cl1);
        mma3x(d0, ah, al, bh0, bh1, bl0, bl1);
        mma3x(d1, ah, al, ch0, ch1, cl0, cl1);
    }

    float* rw = red + warp * 256;
    rw[g * 16 + 2 * t]            = d0[0];
    rw[g * 16 + 2 * t + 1]        = d0[1];
    rw[(g + 8) * 16 + 2 * t]      = d0[2];
    rw[(g + 8) * 16 + 2 * t + 1]  = d0[3];
    rw[g * 16 + 8 + 2 * t]        = d1[0];
    rw[g * 16 + 8 + 2 * t + 1]    = d1[1];
    rw[(g + 8) * 16 + 8 + 2 * t]  = d1[2];
    rw[(g + 8) * 16 + 8 + 2 * t + 1] = d1[3];
    __syncthreads();

    for (int o = tid; o < 256; o += 128) {
        float v = red[o] + red[256 + o] + red[512 + o] + red[768 + o];
        int r = o >> 4, c = o & 15;
        int row = m0 + r, col = n0 + c;
        if (bias) v += bias[col];
        if (act) v = gelu_f(v);
        if (row < M) C[(long)row * N + col] = v;
    }
}

// grid (N/16, ceil(M/16), zsplit). bias only slice 0; act only with zs==1.
__global__ void __launch_bounds__(128) k_tgemm(
    const float* __restrict__ A, int lda, const float* __restrict__ W, int ldw,
    const float* __restrict__ bias, float* __restrict__ C,
    int M, int N, int K, int act, int bcmod)
{
    __shared__ float red[1024];
    int zs = gridDim.z, s = blockIdx.z;
    int klen = K / zs;
    tgemm_body(A, lda, W, ldw, (s == 0) ? bias : (const float*)0,
               C + (long)s * M * N, M, N, act, bcmod,
               blockIdx.y * 16, blockIdx.x * 16, s * klen, klen, red);
}

// ---------------- head precompute mega-kernel --------------------------------
__global__ void __launch_bounds__(128) k_headpre(
    const float* __restrict__ objf, const float* __restrict__ tctx,
    const float* __restrict__ pe1_w,
    const float* __restrict__ ca_in_w, const float* __restrict__ ca_in_b,
    const float* __restrict__ pred_w, const float* __restrict__ pred_b,
    const float* __restrict__ ex_w, const float* __restrict__ ex_b,
    const float* __restrict__ pe2_w, const float* __restrict__ pe2_b)
{
    __shared__ float red[1024];
    int blk = blockIdx.x;
    if (blk < 1280) {
        int which = blk >= 640;
        int idx = blk - which * 640;
        tgemm_body(objf, H, pe1_w + which * H, 3 * H, 0, which ? g_ow : g_sw,
                   BSZ * NOBJ, H, 0, 0, (idx >> 5) * 16, (idx & 31) * 16, 0, H, red);
        return;
    }
    blk -= 1280;
    if (blk < 1280) {
        int l = blk >= 640;
        int idx = blk - l * 640;
        tgemm_body(tctx, H, ca_in_w + (long)l * 3 * H * H + (long)H * H, H,
                   ca_in_b + l * 3 * H + H, g_kv + (long)l * BSZ * TC * 2 * H,
                   BSZ * TC, 2 * H, 0, 0, (idx >> 6) * 16, (idx & 63) * 16, 0, H, red);
        return;
    }
    int j = blk - 1280;   // 0..31
    int tid = threadIdx.x;
    int c0 = tid * 4;
    if (j >= 27) {
        *(float4*)&g_wf[j * H + c0] = make_float4(0.f, 0.f, 0.f, 0.f);
        if (tid == 0) g_bf[j] = 0.f;
        return;
    }
    const float* wc = (j < NPRED) ? (pred_w + j * H) : ex_w;
    float4 s = make_float4(0.f, 0.f, 0.f, 0.f);
    for (int o = 0; o < H; o++) {
        float w = wc[o];
        float4 p = *(const float4*)&pe2_w[(long)o * H + c0];
        s.x += w * p.x; s.y += w * p.y; s.z += w * p.z; s.w += w * p.w;
    }
    *(float4*)&g_wf[j * H + c0] = s;
    __shared__ float sm[4];
    float bsum = 0.f;
    for (int o = tid; o < H; o += 128) bsum += wc[o] * pe2_b[o];
    #pragma unroll
    for (int o = 16; o; o >>= 1) bsum += __shfl_xor_sync(0xffffffffu, bsum, o);
    if ((tid & 31) == 0) sm[tid >> 5] = bsum;
    __syncthreads();
    if (tid == 0) g_bf[j] = ((j < NPRED) ? pred_b[j] : ex_b[0]) + sm[0] + sm[1] + sm[2] + sm[3];
}

// ---------------- fused attention sublayer: one block per batch --------------
// attn (scores/softmax/P@V) -> out-proj (scalar warp-dot) -> residual -> LN.
// No cross-block dependency: block b owns rows [b*Tq, (b+1)*Tq).
__global__ void __launch_bounds__(256) k_attnsub(
    const float* __restrict__ q, int qstride,
    const float* __restrict__ kv, int kvstride, int koff, int voff,
    int Tq, int Tk,
    const float* __restrict__ ow, const float* __restrict__ ob,
    const float* __restrict__ res, int resmod,
    const float* __restrict__ lw, const float* __restrict__ lb,
    float* __restrict__ xout)
{
    __shared__ float qs[MAXF * SP];     // q tile; reused as out-proj result
    __shared__ float ks[TC * SP];
    __shared__ float att[MAXF * SP];
    __shared__ float sc[NH * MAXF * (TC + 1)];
    int b = blockIdx.x;
    int t = threadIdx.x;
    int w = t >> 5, lane = t & 31;

    for (int e = t; e < Tq * H; e += 256) {
        int r = e >> 9, c = e & (H - 1);
        qs[r * SP + c] = q[(long)(b * Tq + r) * qstride + c];
    }
    for (int e = t; e < Tk * H; e += 256) {
        int r = e >> 9, c = e & (H - 1);
        ks[r * SP + c] = kv[(long)(b * Tk + r) * kvstride + koff + c];
    }
    __syncthreads();

    // scores
    for (int idx = t; idx < NH * Tq * Tk; idx += 256) {
        int h = idx / (Tq * Tk);
        int rr = idx - h * Tq * Tk;
        int ti = rr / Tk, tj = rr - ti * Tk;
        int c0 = h * DH;
        float s = 0.f;
        #pragma unroll 16
        for (int d = 0; d < DH; d++) s += qs[ti * SP + c0 + d] * ks[tj * SP + c0 + d];
        sc[(h * MAXF + ti) * (TC + 1) + tj] = s * 0.125f;
    }
    __syncthreads();
    // softmax
    for (int idx = t; idx < NH * Tq; idx += 256) {
        int h = idx / Tq, ti = idx - h * Tq;
        float* row = &sc[(h * MAXF + ti) * (TC + 1)];
        float mx = -1e30f;
        for (int j = 0; j < Tk; j++) mx = fmaxf(mx, row[j]);
        float sum = 0.f;
        for (int j = 0; j < Tk; j++) { float e = expf(row[j] - mx); row[j] = e; sum += e; }
        float inv = 1.f / sum;
        for (int j = 0; j < Tk; j++) row[j] *= inv;
    }
    __syncthreads();
    // att = P @ V  (v read from gmem, L1-cached)
    for (int e = t; e < Tq * H; e += 256) {
        int ti = e >> 9, c = e & (H - 1);
        int h = c >> 6;
        const float* p = &sc[(h * MAXF + ti) * (TC + 1)];
        float o = 0.f;
        for (int j = 0; j < Tk; j++)
            o += p[j] * kv[(long)(b * Tk + j) * kvstride + voff + c];
        att[ti * SP + c] = o;
    }
    __syncthreads();

    // out-proj: 8 warps x 64 cols each; results into qs (reused as proj buffer)
    for (int pass = 0; pass < 8; pass++) {
        int n0 = w * 64 + pass * 8;
        float acc[MAXF][8];
        #pragma unroll
        for (int i = 0; i < MAXF; i++)
            #pragma unroll
            for (int j = 0; j < 8; j++) acc[i][j] = 0.f;
        for (int kc = 0; kc < H; kc += 128) {
            float4 a[MAXF];
            for (int ti = 0; ti < Tq; ti++)
                a[ti] = *(const float4*)&att[ti * SP + kc + lane * 4];
            #pragma unroll
            for (int j = 0; j < 8; j++) {
                float4 bv = *(const float4*)(ow + (long)(n0 + j) * H + kc + lane * 4);
                for (int ti = 0; ti < Tq; ti++)
                    acc[ti][j] += a[ti].x * bv.x + a[ti].y * bv.y + a[ti].z * bv.z + a[ti].w * bv.w;
            }
        }
        for (int ti = 0; ti < Tq; ti++) {
            #pragma unroll
            for (int j = 0; j < 8; j++) {
                float v = wred(acc[ti][j]);
                if (lane == 0) qs[ti * SP + n0 + j] = v + ob[n0 + j];
            }
        }
    }
    __syncthreads();

    // residual + LN: warp w handles row w (w < Tq); all data in smem/registers
    if (w < Tq) {
        long row = (long)b * Tq + w;
        long rr = resmod ? (row % resmod) : row;
        float4 vv[4];
        float s1 = 0.f, s2 = 0.f;
        #pragma unroll
        for (int qq = 0; qq < 4; qq++) {
            int c = lane * 4 + qq * 128;
            float4 pv = *(const float4*)&qs[w * SP + c];
            float4 rv = *(const float4*)&res[rr * H + c];
            float4 v = make_float4(pv.x + rv.x, pv.y + rv.y, pv.z + rv.z, pv.w + rv.w);
            vv[qq] = v;
            s1 += v.x + v.y + v.z + v.w;
            s2 += v.x * v.x + v.y * v.y + v.z * v.z + v.w * v.w;
        }
        s1 = wred(s1); s2 = wred(s2);
        float mean = s1 * (1.f / H);
        float var = s2 * (1.f / H) - mean * mean;
        float inv = rsqrtf(var + 1e-5f);
        #pragma unroll
        for (int qq = 0; qq < 4; qq++) {
            int c = lane * 4 + qq * 128;
            float4 lwv = *(const float4*)&lw[c];
            float4 lbv = *(const float4*)&lb[c];
            float4 y;
            y.x = (vv[qq].x - mean) * inv * lwv.x + lbv.x;
            y.y = (vv[qq].y - mean) * inv * lwv.y + lbv.y;
            y.z = (vv[qq].z - mean) * inv * lwv.z + lbv.z;
            y.w = (vv[qq].w - mean) * inv * lwv.w + lbv.w;
            *(float4*)&xout[row * H + c] = y;
        }
    }
}

// ---------------- layernorm: out = LN(sum_s x_s + res); optional 2nd LN -> ctx
__global__ void ln_kernel(const float* __restrict__ x, int ssz, int nsum,
                          const float* __restrict__ res, int resmod,
                          const float* __restrict__ w, const float* __restrict__ b,
                          float* __restrict__ out,
                          const float* __restrict__ fw, const float* __restrict__ fb,
                          float* __restrict__ ctxout)
{
    int row = blockIdx.x;
    int t = threadIdx.x;
    __shared__ float sm1[4], sm2[4];
    float v[4];
    long rrow = resmod ? (row % resmod) : row;
    float s1 = 0.f, s2 = 0.f;
    #pragma unroll
    for (int i = 0; i < 4; i++) {
        int c = t + i * 128;
        float val = res[rrow * H + c];
        for (int s = 0; s < nsum; s++) val += x[(long)s * ssz + (long)row * H + c];
        v[i] = val; s1 += val; s2 += val * val;
    }
    #pragma unroll
    for (int o = 16; o; o >>= 1) {
        s1 += __shfl_xor_sync(0xffffffffu, s1, o);
        s2 += __shfl_xor_sync(0xffffffffu, s2, o);
    }
    if ((t & 31) == 0) { sm1[t >> 5] = s1; sm2[t >> 5] = s2; }
    __syncthreads();
    float S1 = sm1[0] + sm1[1] + sm1[2] + sm1[3];
    float S2 = sm2[0] + sm2[1] + sm2[2] + sm2[3];
    float mean = S1 * (1.f / H);
    float var = S2 * (1.f / H) - mean * mean;
    float inv = rsqrtf(var + 1e-5f);
    float y[4];
    #pragma unroll
    for (int i = 0; i < 4; i++) {
        int c = t + i * 128;
        y[i] = (v[i] - mean) * inv * w[c] + b[c];
        out[(long)row * H + c] = y[i];
    }
    if (fw) {
        float t1 = 0.f, t2 = 0.f;
        #pragma unroll
        for (int i = 0; i < 4; i++) { t1 += y[i]; t2 += y[i] * y[i]; }
        #pragma unroll
        for (int o = 16; o; o >>= 1) {
            t1 += __shfl_xor_sync(0xffffffffu, t1, o);
            t2 += __shfl_xor_sync(0xffffffffu, t2, o);
        }
        __syncthreads();
        if ((t & 31) == 0) { sm1[t >> 5] = t1; sm2[t >> 5] = t2; }
        __syncthreads();
        float T1 = sm1[0] + sm1[1] + sm1[2] + sm1[3];
        float T2 = sm2[0] + sm2[1] + sm2[2] + sm2[3];
        float m2 = T1 * (1.f / H);
        float v2 = T2 * (1.f / H) - m2 * m2;
        float i2 = rsqrtf(v2 + 1e-5f);
        #pragma unroll
        for (int i = 0; i < 4; i++) {
            int c = t + i * 128;
            ctxout[(long)row * H + c] = (y[i] - m2) * i2 * fw[c] + fb[c];
        }
    }
}

// ---------------- fused pair head (tensor-core) ------------------------------
__global__ void __launch_bounds__(128) k_pairh(float* __restrict__ out, int Fh, int Rtot)
{
    __shared__ float hs[16 * 516];
    __shared__ float red[4 * 16 * 32];
    int tid = threadIdx.x, warp = tid >> 5, lane = tid & 31;
    int g = lane >> 2, t = lane & 3;
    int row0 = blockIdx.x * 16;

    for (int e = tid; e < 16 * H; e += 128) {
        int r = e >> 9, c = e & (H - 1);
        int row = row0 + r;
        int p = row % NP;
        int bfi = row / NP;
        int f = bfi % Fh;
        int b = bfi / Fh;
        int i = p / (NOBJ - 1);
        int jr = p % (NOBJ - 1);
        int jo = jr + (jr >= i ? 1 : 0);
        float hv = g_sw[(long)(b * NOBJ + i) * H + c] + g_ow[(long)(b * NOBJ + jo) * H + c]
                 + g_cw[(long)(b * Fh + f) * H + c];
        hs[r * 516 + c] = gelu_f(hv);
    }
    __syncthreads();

    float d[4][4];
    #pragma unroll
    for (int f = 0; f < 4; f++)
        #pragma unroll
        for (int q = 0; q < 4; q++) d[f][q] = 0.f;
    int kb = warp * 128;
    #pragma unroll 2
    for (int kk = kb; kk < kb + 128; kk += 8) {
        unsigned ah[4], al[4];
        split32(hs[g * 516 + kk + t],           ah[0], al[0]);
        split32(hs[(g + 8) * 516 + kk + t],     ah[1], al[1]);
        split32(hs[g * 516 + kk + t + 4],       ah[2], al[2]);
        split32(hs[(g + 8) * 516 + kk + t + 4], ah[3], al[3]);
        #pragma unroll
        for (int f = 0; f < 4; f++) {
            unsigned bh0, bl0, bh1, bl1;
            split32(g_wf[(long)(f * 8 + g) * H + kk + t],     bh0, bl0);
            split32(g_wf[(long)(f * 8 + g) * H + kk + t + 4], bh1, bl1);
            mma3x(d[f], ah, al, bh0, bh1, bl0, bl1);
        }
    }
    float* rw = red + warp * 512;
    #pragma unroll
    for (int f = 0; f < 4; f++) {
        int cb = f * 8;
        rw[g * 32 + cb + 2 * t]           = d[f][0];
        rw[g * 32 + cb + 2 * t + 1]       = d[f][1];
        rw[(g + 8) * 32 + cb + 2 * t]     = d[f][2];
        rw[(g + 8) * 32 + cb + 2 * t + 1] = d[f][3];
    }
    __syncthreads();
    for (int o = tid; o < 512; o += 128) {
        float v = red[o] + red[512 + o] + red[1024 + o] + red[1536 + o];
        int r = o >> 5, c = o & 31;
        v += g_bf[c];
        int row = row0 + r;
        if (c < NPRED)       out[(long)row * NPRED + c] = v;
        else if (c == NPRED) out[(long)Rtot * NPRED + row] = v;
    }
}

// ---------------- host orchestration ----------------
extern "C" void kernel_launch(void* const* d_in, const int* in_sizes, int n_in,
                              void* d_out, int out_size)
{
    const float* tctx    = (const float*)d_in[0];
    const float* objf    = (const float*)d_in[1];
    const float* fq      = (const float*)d_in[2];
    const float* sa_in_w = (const float*)d_in[3];
    const float* sa_in_b = (const float*)d_in[4];
    const float* sa_out_w= (const float*)d_in[5];
    const float* sa_out_b= (const float*)d_in[6];
    const float* ca_in_w = (const float*)d_in[7];
    const float* ca_in_b = (const float*)d_in[8];
    const float* ca_out_w= (const float*)d_in[9];
    const float* ca_out_b= (const float*)d_in[10];
    const float* ff1_w   = (const float*)d_in[11];
    const float* ff1_b   = (const float*)d_in[12];
    const float* ff2_w   = (const float*)d_in[13];
    const float* ff2_b   = (const float*)d_in[14];
    const float* n1_w    = (const float*)d_in[15];
    const float* n1_b    = (const float*)d_in[16];
    const float* n2_w    = (const float*)d_in[17];
    const float* n2_b    = (const float*)d_in[18];
    const float* n3_w    = (const float*)d_in[19];
    const float* n3_b    = (const float*)d_in[20];
    const float* norm_w  = (const float*)d_in[21];
    const float* norm_b  = (const float*)d_in[22];
    const float* pe1_w   = (const float*)d_in[23];
    const float* pe1_b   = (const float*)d_in[24];
    const float* pe2_w   = (const float*)d_in[25];
    const float* pe2_b   = (const float*)d_in[26];
    const float* pred_w  = (const float*)d_in[27];
    const float* pred_b  = (const float*)d_in[28];
    const float* ex_w    = (const float*)d_in[29];
    const float* ex_b    = (const float*)d_in[30];
    (void)in_sizes; (void)n_in;

    int Fh = out_size / (BSZ * NP * (NPRED + 1));
    if (Fh < 1) Fh = 1;
    if (Fh > MAXF) Fh = MAXF;
    int Mq = BSZ * Fh;
    int MT = (Mq + 15) / 16;

    float *px, *pqkv, *pkv, *pproj, *pffh, *pctx, *pcw;
    cudaGetSymbolAddress((void**)&px,    g_px);
    cudaGetSymbolAddress((void**)&pqkv,  g_qkv);
    cudaGetSymbolAddress((void**)&pkv,   g_kv);
    cudaGetSymbolAddress((void**)&pproj, g_proj);
    cudaGetSymbolAddress((void**)&pffh,  g_ffh);
    cudaGetSymbolAddress((void**)&pctx,  g_ctx);
    cudaGetSymbolAddress((void**)&pcw,   g_cw);

    // 1) all decoder-independent precompute in one launch (2592 blocks)
    k_headpre<<<2592, 128>>>(objf, tctx, pe1_w, ca_in_w, ca_in_b,
                             pred_w, pred_b, ex_w, ex_b, pe2_w, pe2_b);

    for (int l = 0; l < NLAY; l++) {
        // SA qkv (layer0 reads broadcast fq)
        k_tgemm<<<dim3(3 * H / 16, MT, 1), 128>>>(
            (l == 0) ? fq : px, H, sa_in_w + (long)l * 3 * H * H, H,
            sa_in_b + l * 3 * H, pqkv, Mq, 3 * H, H, 0, (l == 0) ? Fh : 0);
        // fused SA: attn + out-proj + residual + LN
        k_attnsub<<<BSZ, 256>>>(pqkv, 3 * H, pqkv, 3 * H, H, 2 * H, Fh, Fh,
                                sa_out_w + (long)l * H * H, sa_out_b + l * H,
                                (l == 0) ? fq : px, (l == 0) ? Fh : 0,
                                n1_w + l * H, n1_b + l * H, px);
        // CA q-proj (kv precomputed in headpre)
        k_tgemm<<<dim3(H / 16, MT, 1), 128>>>(
            px, H, ca_in_w + (long)l * 3 * H * H, H, ca_in_b + l * 3 * H,
            pqkv, Mq, H, H, 0, 0);
        const float* kvl = pkv + (long)l * BSZ * TC * 2 * H;
        // fused CA: attn + out-proj + residual + LN
        k_attnsub<<<BSZ, 256>>>(pqkv, H, kvl, 2 * H, 0, H, Fh, TC,
                                ca_out_w + (long)l * H * H, ca_out_b + l * H,
                                px, 0,
                                n2_w + l * H, n2_b + l * H, px);
        // FFN
        k_tgemm<<<dim3(FFD / 16, MT, 1), 128>>>(
            px, H, ff1_w + (long)l * FFD * H, H, ff1_b + l * FFD,
            pffh, Mq, FFD, H, 1, 0);
        k_tgemm<<<dim3(H / 16, MT, 4), 128>>>(
            pffh, FFD, ff2_w + (long)l * H * FFD, FFD, ff2_b + l * H,
            pproj, Mq, H, FFD, 0, 0);
        int last = (l == NLAY - 1);
        ln_kernel<<<Mq, 128>>>(pproj, Mq * H, 4, px, 0,
                               n3_w + l * H, n3_b + l * H, px,
                               last ? norm_w : nullptr, last ? norm_b : nullptr, pctx);
    }

    // ctx projection through pe1 ctx slice
    k_tgemm<<<dim3(H / 16, MT, 1), 128>>>(
        pctx, H, pe1_w + 2 * H, 3 * H, pe1_b, pcw, Mq, H, H, 0, 0);

    // fused pair head (tensor-core)
    int Rtot = BSZ * Fh * NP;
    k_pairh<<<Rtot / 16, 128>>>((float*)d_out, Fh, Rtot);
}